// round 10
// baseline (speedup 1.0000x reference)
#include <cuda_runtime.h>

// out[h1,w1,c1,h2,w2,c2] = g^(|dh|+|dw|+|dc|) * (1 + spec_pe[c1,c2]*mean[h1,w1,c1]) * decay[c1]
// mean[h1,w1,c1] = Sh[h1]*Sw[w1]*Sc[c1] / (H*W*C), separable geometric sums.
// H=W=32, C=8. Output: 1024 * 65536 floats = 268.4 MB, pure write-bound.
//
// R10 = R9 (512-thread CTAs, verified WIN: ncu 40.03us, bench 44.64us) with
// __launch_bounds__(512, 4): cap regs at 32 -> 4 CTAs/SM = 64 warps (100%
// theoretical occupancy, up from 48/75%). R9 showed occupancy moves DRAM%
// for this write stream (occ 51->62% gave DRAM 62->66%); body unchanged so
// the reg cap is the only variable (R3's regression was its loop change).

#define GAMMA 0.9f

__global__ __launch_bounds__(512, 4) void mrp3d_kernel(const float* __restrict__ decay,
                                                       const float* __restrict__ spec_pe,
                                                       float* __restrict__ out) {
    __shared__ float sPow[40];    // gamma^d, d = 0..39 (max needed: 31)
    __shared__ float4 sCoef[16];  // fused coef [c1][c2-half]: decay*(1+spec*mean)*g^|c1-c2|

    const int h1 = blockIdx.x >> 5;
    const int w1 = blockIdx.x & 31;
    const int t  = threadIdx.x;

    // Build gamma^d table (iterative product; few-ulp error, fine for 1e-3 tol)
    if (t < 40) {
        float p = 1.0f;
        for (int i = 0; i < t; ++i) p *= GAMMA;
        sPow[t] = p;
    }
    __syncthreads();

    // Build fused 8x8 coefficient table for this (h1,w1)
    if (t < 64) {
        const int c1 = t >> 3;
        const int c2 = t & 7;
        float Sh = 0.0f, Sw = 0.0f, Sc = 0.0f;
        #pragma unroll
        for (int j = 0; j < 32; ++j) {
            Sh += sPow[abs(h1 - j)];
            Sw += sPow[abs(w1 - j)];
        }
        #pragma unroll
        for (int j = 0; j < 8; ++j) Sc += sPow[abs(c1 - j)];
        const float mean = Sh * Sw * Sc * (1.0f / 8192.0f);
        const float coef = decay[c1] * (1.0f + spec_pe[c1 * 8 + c2] * mean) * sPow[abs(c1 - c2)];
        reinterpret_cast<float*>(sCoef)[t] = coef;
    }
    __syncthreads();

    // Output slice for this (h1,w1): 65536 floats = 16384 float4, contiguous.
    float4* __restrict__ outv = reinterpret_cast<float4*>(out) + (size_t)blockIdx.x * 16384;

    // float4 index within c1-slice: r = (h2*32 + w2)*2 + half, r in [0,2048)
    // For 512 threads: half = t&1, w2 = (t>>1)&31, h2base = t>>6 (0..7),
    // h2 = h2base + 8*it, it in [0,4); r = t + 512*it.
    const int half    = t & 1;
    const int w2      = (t >> 1) & 31;
    const int h2base  = t >> 6;
    const float sW    = sPow[abs(w1 - w2)];

    #pragma unroll
    for (int c1 = 0; c1 < 8; ++c1) {
        const float4 cf = sCoef[(c1 << 1) | half];
        float4* outc = outv + c1 * 2048;
        #pragma unroll
        for (int it = 0; it < 4; ++it) {
            const int h2 = h2base + (it << 3);
            const int r  = t + (it << 9);
            const float s = sPow[abs(h1 - h2)] * sW;
            float4 o;
            o.x = s * cf.x;
            o.y = s * cf.y;
            o.z = s * cf.z;
            o.w = s * cf.w;
            outc[r] = o;
        }
    }
}

extern "C" void kernel_launch(void* const* d_in, const int* in_sizes, int n_in,
                              void* d_out, int out_size) {
    // Inputs: x (unused, 524288 elems), decay (8), spec_pe (64) — identify by size.
    const float* decay   = nullptr;
    const float* spec_pe = nullptr;
    for (int i = 0; i < n_in; ++i) {
        if (in_sizes[i] == 8)       decay   = (const float*)d_in[i];
        else if (in_sizes[i] == 64) spec_pe = (const float*)d_in[i];
    }
    mrp3d_kernel<<<1024, 512>>>(decay, spec_pe, (float*)d_out);
}

// round 11
// speedup vs baseline: 1.0245x; 1.0245x over previous
#include <cuda_runtime.h>

// out[h1,w1,c1,h2,w2,c2] = g^(|dh|+|dw|+|dc|) * (1 + spec_pe[c1,c2]*mean[h1,w1,c1]) * decay[c1]
// mean[h1,w1,c1] = Sh[h1]*Sw[w1]*Sc[c1] / (H*W*C), separable geometric sums.
// H=W=32, C=8. Output: 1024 * 65536 floats = 268.4 MB, pure write-bound.
//
// R11 = R9 exact (verified best: ncu 40.03us, bench 44.64us): 512-thread CTAs,
// natural 39-reg allocation (NO min-blocks clause). R10 proved forcing 32 regs
// for 100% occupancy regresses (DRAM 65.9->62.2%, ncu 40.0->42.3) — never
// constrain ptxas below its natural choice for this kernel. Reproducibility
// confirmation of the R9 win.

#define GAMMA 0.9f

__global__ __launch_bounds__(512) void mrp3d_kernel(const float* __restrict__ decay,
                                                    const float* __restrict__ spec_pe,
                                                    float* __restrict__ out) {
    __shared__ float sPow[40];    // gamma^d, d = 0..39 (max needed: 31)
    __shared__ float4 sCoef[16];  // fused coef [c1][c2-half]: decay*(1+spec*mean)*g^|c1-c2|

    const int h1 = blockIdx.x >> 5;
    const int w1 = blockIdx.x & 31;
    const int t  = threadIdx.x;

    // Build gamma^d table (iterative product; few-ulp error, fine for 1e-3 tol)
    if (t < 40) {
        float p = 1.0f;
        for (int i = 0; i < t; ++i) p *= GAMMA;
        sPow[t] = p;
    }
    __syncthreads();

    // Build fused 8x8 coefficient table for this (h1,w1)
    if (t < 64) {
        const int c1 = t >> 3;
        const int c2 = t & 7;
        float Sh = 0.0f, Sw = 0.0f, Sc = 0.0f;
        #pragma unroll
        for (int j = 0; j < 32; ++j) {
            Sh += sPow[abs(h1 - j)];
            Sw += sPow[abs(w1 - j)];
        }
        #pragma unroll
        for (int j = 0; j < 8; ++j) Sc += sPow[abs(c1 - j)];
        const float mean = Sh * Sw * Sc * (1.0f / 8192.0f);
        const float coef = decay[c1] * (1.0f + spec_pe[c1 * 8 + c2] * mean) * sPow[abs(c1 - c2)];
        reinterpret_cast<float*>(sCoef)[t] = coef;
    }
    __syncthreads();

    // Output slice for this (h1,w1): 65536 floats = 16384 float4, contiguous.
    float4* __restrict__ outv = reinterpret_cast<float4*>(out) + (size_t)blockIdx.x * 16384;

    // float4 index within c1-slice: r = (h2*32 + w2)*2 + half, r in [0,2048)
    // For 512 threads: half = t&1, w2 = (t>>1)&31, h2base = t>>6 (0..7),
    // h2 = h2base + 8*it, it in [0,4); r = t + 512*it.
    const int half    = t & 1;
    const int w2      = (t >> 1) & 31;
    const int h2base  = t >> 6;
    const float sW    = sPow[abs(w1 - w2)];

    #pragma unroll
    for (int c1 = 0; c1 < 8; ++c1) {
        const float4 cf = sCoef[(c1 << 1) | half];
        float4* outc = outv + c1 * 2048;
        #pragma unroll
        for (int it = 0; it < 4; ++it) {
            const int h2 = h2base + (it << 3);
            const int r  = t + (it << 9);
            const float s = sPow[abs(h1 - h2)] * sW;
            float4 o;
            o.x = s * cf.x;
            o.y = s * cf.y;
            o.z = s * cf.z;
            o.w = s * cf.w;
            outc[r] = o;
        }
    }
}

extern "C" void kernel_launch(void* const* d_in, const int* in_sizes, int n_in,
                              void* d_out, int out_size) {
    // Inputs: x (unused, 524288 elems), decay (8), spec_pe (64) — identify by size.
    const float* decay   = nullptr;
    const float* spec_pe = nullptr;
    for (int i = 0; i < n_in; ++i) {
        if (in_sizes[i] == 8)       decay   = (const float*)d_in[i];
        else if (in_sizes[i] == 64) spec_pe = (const float*)d_in[i];
    }
    mrp3d_kernel<<<1024, 512>>>(decay, spec_pe, (float*)d_out);
}

// round 12
// speedup vs baseline: 1.0395x; 1.0146x over previous
#include <cuda_runtime.h>

// out[h1,w1,c1,h2,w2,c2] = g^(|dh|+|dw|+|dc|) * (1 + spec_pe[c1,c2]*mean[h1,w1,c1]) * decay[c1]
// mean[h1,w1,c1] = Sh[h1]*Sw[w1]*Sc[c1] / (H*W*C), separable geometric sums.
// H=W=32, C=8. Output: 1024 * 65536 floats = 268.4 MB, pure write-bound.
//
// R12 = R11 (512-thread CTAs, natural regs — verified best: ncu 39.10us,
// bench 44.42us) + 256-bit stores (st.global.v8.b32). At the new operating
// point L1 hit 70.2% (highest counter); halving store instructions/L1
// wavefronts attacks it. One thread writes one full 8-float c2-row.

#define GAMMA 0.9f

__device__ __forceinline__ void stg256(float* p, float x0, float x1, float x2, float x3,
                                       float x4, float x5, float x6, float x7) {
    asm volatile("st.global.v8.b32 [%0], {%1,%2,%3,%4,%5,%6,%7,%8};"
                 :: "l"(p),
                    "r"(__float_as_uint(x0)), "r"(__float_as_uint(x1)),
                    "r"(__float_as_uint(x2)), "r"(__float_as_uint(x3)),
                    "r"(__float_as_uint(x4)), "r"(__float_as_uint(x5)),
                    "r"(__float_as_uint(x6)), "r"(__float_as_uint(x7))
                 : "memory");
}

__global__ __launch_bounds__(512) void mrp3d_kernel(const float* __restrict__ decay,
                                                    const float* __restrict__ spec_pe,
                                                    float* __restrict__ out) {
    __shared__ float sPow[40];    // gamma^d, d = 0..39 (max needed: 31)
    __shared__ float4 sCoef[16];  // fused coef [c1][c2-half]: decay*(1+spec*mean)*g^|c1-c2|

    const int h1 = blockIdx.x >> 5;
    const int w1 = blockIdx.x & 31;
    const int t  = threadIdx.x;

    // Build gamma^d table (iterative product; few-ulp error, fine for 1e-3 tol)
    if (t < 40) {
        float p = 1.0f;
        for (int i = 0; i < t; ++i) p *= GAMMA;
        sPow[t] = p;
    }
    __syncthreads();

    // Build fused 8x8 coefficient table for this (h1,w1)
    if (t < 64) {
        const int c1 = t >> 3;
        const int c2 = t & 7;
        float Sh = 0.0f, Sw = 0.0f, Sc = 0.0f;
        #pragma unroll
        for (int j = 0; j < 32; ++j) {
            Sh += sPow[abs(h1 - j)];
            Sw += sPow[abs(w1 - j)];
        }
        #pragma unroll
        for (int j = 0; j < 8; ++j) Sc += sPow[abs(c1 - j)];
        const float mean = Sh * Sw * Sc * (1.0f / 8192.0f);
        const float coef = decay[c1] * (1.0f + spec_pe[c1 * 8 + c2] * mean) * sPow[abs(c1 - c2)];
        reinterpret_cast<float*>(sCoef)[t] = coef;
    }
    __syncthreads();

    // Output slice for this (h1,w1): 65536 floats, contiguous.
    float* __restrict__ outb = out + (size_t)blockIdx.x * 65536;

    // One thread per (h2,w2) c2-row (8 floats = 32B = one STG.256).
    // 1024 rows / 512 threads: w2 = t&31, h2base = t>>5 (0..15),
    // h2 = h2base + 16*it, it in [0,2).
    const int w2     = t & 31;
    const int h2base = t >> 5;
    const float sW   = sPow[abs(w1 - w2)];

    #pragma unroll
    for (int c1 = 0; c1 < 8; ++c1) {
        const float4 cfLo = sCoef[(c1 << 1) | 0];
        const float4 cfHi = sCoef[(c1 << 1) | 1];
        float* outc = outb + c1 * 8192;
        #pragma unroll
        for (int it = 0; it < 2; ++it) {
            const int h2 = h2base + (it << 4);
            const float s = sPow[abs(h1 - h2)] * sW;
            float* p = outc + (((h2 << 5) | w2) << 3);
            stg256(p, s * cfLo.x, s * cfLo.y, s * cfLo.z, s * cfLo.w,
                      s * cfHi.x, s * cfHi.y, s * cfHi.z, s * cfHi.w);
        }
    }
}

extern "C" void kernel_launch(void* const* d_in, const int* in_sizes, int n_in,
                              void* d_out, int out_size) {
    // Inputs: x (unused, 524288 elems), decay (8), spec_pe (64) — identify by size.
    const float* decay   = nullptr;
    const float* spec_pe = nullptr;
    for (int i = 0; i < n_in; ++i) {
        if (in_sizes[i] == 8)       decay   = (const float*)d_in[i];
        else if (in_sizes[i] == 64) spec_pe = (const float*)d_in[i];
    }
    mrp3d_kernel<<<1024, 512>>>(decay, spec_pe, (float*)d_out);
}

// round 13
// speedup vs baseline: 1.0464x; 1.0066x over previous
#include <cuda_runtime.h>

// out[h1,w1,c1,h2,w2,c2] = g^(|dh|+|dw|+|dc|) * (1 + spec_pe[c1,c2]*mean[h1,w1,c1]) * decay[c1]
// mean[h1,w1,c1] = Sh[h1]*Sw[w1]*Sc[c1] / (H*W*C), separable geometric sums.
// H=W=32, C=8. Output: 1024 * 65536 floats = 268.4 MB, pure write-bound.
//
// R13 = R12 (512-thread CTAs + STG.256, verified best bench 43.78us) with
// evict-first L2 policy on the 256-bit store (st.global.cs.v8.b32). Write-once
// stream -> shorter dirty-line dwell in L2, smoother drain between replays.

#define GAMMA 0.9f

__device__ __forceinline__ void stg256cs(float* p, float x0, float x1, float x2, float x3,
                                         float x4, float x5, float x6, float x7) {
    asm volatile("st.global.cs.v8.b32 [%0], {%1,%2,%3,%4,%5,%6,%7,%8};"
                 :: "l"(p),
                    "r"(__float_as_uint(x0)), "r"(__float_as_uint(x1)),
                    "r"(__float_as_uint(x2)), "r"(__float_as_uint(x3)),
                    "r"(__float_as_uint(x4)), "r"(__float_as_uint(x5)),
                    "r"(__float_as_uint(x6)), "r"(__float_as_uint(x7))
                 : "memory");
}

__global__ __launch_bounds__(512) void mrp3d_kernel(const float* __restrict__ decay,
                                                    const float* __restrict__ spec_pe,
                                                    float* __restrict__ out) {
    __shared__ float sPow[40];    // gamma^d, d = 0..39 (max needed: 31)
    __shared__ float4 sCoef[16];  // fused coef [c1][c2-half]: decay*(1+spec*mean)*g^|c1-c2|

    const int h1 = blockIdx.x >> 5;
    const int w1 = blockIdx.x & 31;
    const int t  = threadIdx.x;

    // Build gamma^d table (iterative product; few-ulp error, fine for 1e-3 tol)
    if (t < 40) {
        float p = 1.0f;
        for (int i = 0; i < t; ++i) p *= GAMMA;
        sPow[t] = p;
    }
    __syncthreads();

    // Build fused 8x8 coefficient table for this (h1,w1)
    if (t < 64) {
        const int c1 = t >> 3;
        const int c2 = t & 7;
        float Sh = 0.0f, Sw = 0.0f, Sc = 0.0f;
        #pragma unroll
        for (int j = 0; j < 32; ++j) {
            Sh += sPow[abs(h1 - j)];
            Sw += sPow[abs(w1 - j)];
        }
        #pragma unroll
        for (int j = 0; j < 8; ++j) Sc += sPow[abs(c1 - j)];
        const float mean = Sh * Sw * Sc * (1.0f / 8192.0f);
        const float coef = decay[c1] * (1.0f + spec_pe[c1 * 8 + c2] * mean) * sPow[abs(c1 - c2)];
        reinterpret_cast<float*>(sCoef)[t] = coef;
    }
    __syncthreads();

    // Output slice for this (h1,w1): 65536 floats, contiguous.
    float* __restrict__ outb = out + (size_t)blockIdx.x * 65536;

    // One thread per (h2,w2) c2-row (8 floats = 32B = one STG.256).
    // 1024 rows / 512 threads: w2 = t&31, h2base = t>>5 (0..15),
    // h2 = h2base + 16*it, it in [0,2). Per (c1,it) the CTA writes a
    // contiguous 16KB block; the full 256KB slice is swept sequentially.
    const int w2     = t & 31;
    const int h2base = t >> 5;
    const float sW   = sPow[abs(w1 - w2)];

    #pragma unroll
    for (int c1 = 0; c1 < 8; ++c1) {
        const float4 cfLo = sCoef[(c1 << 1) | 0];
        const float4 cfHi = sCoef[(c1 << 1) | 1];
        float* outc = outb + c1 * 8192;
        #pragma unroll
        for (int it = 0; it < 2; ++it) {
            const int h2 = h2base + (it << 4);
            const float s = sPow[abs(h1 - h2)] * sW;
            float* p = outc + (((h2 << 5) | w2) << 3);
            stg256cs(p, s * cfLo.x, s * cfLo.y, s * cfLo.z, s * cfLo.w,
                        s * cfHi.x, s * cfHi.y, s * cfHi.z, s * cfHi.w);
        }
    }
}

extern "C" void kernel_launch(void* const* d_in, const int* in_sizes, int n_in,
                              void* d_out, int out_size) {
    // Inputs: x (unused, 524288 elems), decay (8), spec_pe (64) — identify by size.
    const float* decay   = nullptr;
    const float* spec_pe = nullptr;
    for (int i = 0; i < n_in; ++i) {
        if (in_sizes[i] == 8)       decay   = (const float*)d_in[i];
        else if (in_sizes[i] == 64) spec_pe = (const float*)d_in[i];
    }
    mrp3d_kernel<<<1024, 512>>>(decay, spec_pe, (float*)d_out);
}

// round 14
// speedup vs baseline: 1.0557x; 1.0089x over previous
#include <cuda_runtime.h>

// out[h1,w1,c1,h2,w2,c2] = g^(|dh|+|dw|+|dc|) * (1 + spec_pe[c1,c2]*mean[h1,w1,c1]) * decay[c1]
// mean[h1,w1,c1] = Sh[h1]*Sw[w1]*Sc[c1] / (H*W*C), separable geometric sums.
// H=W=32, C=8. Output: 1024 * 65536 floats = 268.4 MB, pure write-bound.
//
// R14 = R13 (512 threads + STG.256 + .cs, verified best bench 43.49us) with
// the store policy moved one step further: write-through (st.global.wt.v8).
// Write-once never-read stream: skip dirty-line allocation in L2 entirely.
// Stores are perfectly coalesced (1KB/warp) = ideal write-combining shape.

#define GAMMA 0.9f

__device__ __forceinline__ void stg256wt(float* p, float x0, float x1, float x2, float x3,
                                         float x4, float x5, float x6, float x7) {
    asm volatile("st.global.wt.v8.b32 [%0], {%1,%2,%3,%4,%5,%6,%7,%8};"
                 :: "l"(p),
                    "r"(__float_as_uint(x0)), "r"(__float_as_uint(x1)),
                    "r"(__float_as_uint(x2)), "r"(__float_as_uint(x3)),
                    "r"(__float_as_uint(x4)), "r"(__float_as_uint(x5)),
                    "r"(__float_as_uint(x6)), "r"(__float_as_uint(x7))
                 : "memory");
}

__global__ __launch_bounds__(512) void mrp3d_kernel(const float* __restrict__ decay,
                                                    const float* __restrict__ spec_pe,
                                                    float* __restrict__ out) {
    __shared__ float sPow[40];    // gamma^d, d = 0..39 (max needed: 31)
    __shared__ float4 sCoef[16];  // fused coef [c1][c2-half]: decay*(1+spec*mean)*g^|c1-c2|

    const int h1 = blockIdx.x >> 5;
    const int w1 = blockIdx.x & 31;
    const int t  = threadIdx.x;

    // Build gamma^d table (iterative product; few-ulp error, fine for 1e-3 tol)
    if (t < 40) {
        float p = 1.0f;
        for (int i = 0; i < t; ++i) p *= GAMMA;
        sPow[t] = p;
    }
    __syncthreads();

    // Build fused 8x8 coefficient table for this (h1,w1)
    if (t < 64) {
        const int c1 = t >> 3;
        const int c2 = t & 7;
        float Sh = 0.0f, Sw = 0.0f, Sc = 0.0f;
        #pragma unroll
        for (int j = 0; j < 32; ++j) {
            Sh += sPow[abs(h1 - j)];
            Sw += sPow[abs(w1 - j)];
        }
        #pragma unroll
        for (int j = 0; j < 8; ++j) Sc += sPow[abs(c1 - j)];
        const float mean = Sh * Sw * Sc * (1.0f / 8192.0f);
        const float coef = decay[c1] * (1.0f + spec_pe[c1 * 8 + c2] * mean) * sPow[abs(c1 - c2)];
        reinterpret_cast<float*>(sCoef)[t] = coef;
    }
    __syncthreads();

    // Output slice for this (h1,w1): 65536 floats, contiguous.
    float* __restrict__ outb = out + (size_t)blockIdx.x * 65536;

    // One thread per (h2,w2) c2-row (8 floats = 32B = one STG.256).
    // 1024 rows / 512 threads: w2 = t&31, h2base = t>>5 (0..15),
    // h2 = h2base + 16*it, it in [0,2). The (c1,it) loop sweeps the CTA's
    // 256KB slice in perfectly sequential 16KB blocks.
    const int w2     = t & 31;
    const int h2base = t >> 5;
    const float sW   = sPow[abs(w1 - w2)];

    #pragma unroll
    for (int c1 = 0; c1 < 8; ++c1) {
        const float4 cfLo = sCoef[(c1 << 1) | 0];
        const float4 cfHi = sCoef[(c1 << 1) | 1];
        float* outc = outb + c1 * 8192;
        #pragma unroll
        for (int it = 0; it < 2; ++it) {
            const int h2 = h2base + (it << 4);
            const float s = sPow[abs(h1 - h2)] * sW;
            float* p = outc + (((h2 << 5) | w2) << 3);
            stg256wt(p, s * cfLo.x, s * cfLo.y, s * cfLo.z, s * cfLo.w,
                        s * cfHi.x, s * cfHi.y, s * cfHi.z, s * cfHi.w);
        }
    }
}

extern "C" void kernel_launch(void* const* d_in, const int* in_sizes, int n_in,
                              void* d_out, int out_size) {
    // Inputs: x (unused, 524288 elems), decay (8), spec_pe (64) — identify by size.
    const float* decay   = nullptr;
    const float* spec_pe = nullptr;
    for (int i = 0; i < n_in; ++i) {
        if (in_sizes[i] == 8)       decay   = (const float*)d_in[i];
        else if (in_sizes[i] == 64) spec_pe = (const float*)d_in[i];
    }
    mrp3d_kernel<<<1024, 512>>>(decay, spec_pe, (float*)d_out);
}

// round 15
// speedup vs baseline: 1.0565x; 1.0007x over previous
#include <cuda_runtime.h>

// out[h1,w1,c1,h2,w2,c2] = g^(|dh|+|dw|+|dc|) * (1 + spec_pe[c1,c2]*mean[h1,w1,c1]) * decay[c1]
// mean[h1,w1,c1] = Sh[h1]*Sw[w1]*Sc[c1] / (H*W*C), separable geometric sums.
// H=W=32, C=8. Output: 1024 * 65536 floats = 268.4 MB, pure write-bound.
//
// R15 = R14 (512 thr + STG.256 + .wt, verified best bench 43.10us) with the
// work quantum halved: grid 2048, each CTA writes HALF a (h1,w1) tile (128KB,
// split by h2 range). Finer wave granularity (2.3 -> 4.6 waves) halves the
// tail imbalance; per-thread store pattern unchanged (8 independent STG.256).

#define GAMMA 0.9f

__device__ __forceinline__ void stg256wt(float* p, float x0, float x1, float x2, float x3,
                                         float x4, float x5, float x6, float x7) {
    asm volatile("st.global.wt.v8.b32 [%0], {%1,%2,%3,%4,%5,%6,%7,%8};"
                 :: "l"(p),
                    "r"(__float_as_uint(x0)), "r"(__float_as_uint(x1)),
                    "r"(__float_as_uint(x2)), "r"(__float_as_uint(x3)),
                    "r"(__float_as_uint(x4)), "r"(__float_as_uint(x5)),
                    "r"(__float_as_uint(x6)), "r"(__float_as_uint(x7))
                 : "memory");
}

__global__ __launch_bounds__(512) void mrp3d_kernel(const float* __restrict__ decay,
                                                    const float* __restrict__ spec_pe,
                                                    float* __restrict__ out) {
    __shared__ float sPow[40];    // gamma^d, d = 0..39 (max needed: 31)
    __shared__ float4 sCoef[16];  // fused coef [c1][c2-half]: decay*(1+spec*mean)*g^|c1-c2|

    const int tile = blockIdx.x >> 1;     // (h1,w1) tile index, 0..1023
    const int hHalf = blockIdx.x & 1;     // which h2 half: [0,16) or [16,32)
    const int h1 = tile >> 5;
    const int w1 = tile & 31;
    const int t  = threadIdx.x;

    // Build gamma^d table (iterative product; few-ulp error, fine for 1e-3 tol)
    if (t < 40) {
        float p = 1.0f;
        for (int i = 0; i < t; ++i) p *= GAMMA;
        sPow[t] = p;
    }
    __syncthreads();

    // Build fused 8x8 coefficient table for this (h1,w1)
    if (t < 64) {
        const int c1 = t >> 3;
        const int c2 = t & 7;
        float Sh = 0.0f, Sw = 0.0f, Sc = 0.0f;
        #pragma unroll
        for (int j = 0; j < 32; ++j) {
            Sh += sPow[abs(h1 - j)];
            Sw += sPow[abs(w1 - j)];
        }
        #pragma unroll
        for (int j = 0; j < 8; ++j) Sc += sPow[abs(c1 - j)];
        const float mean = Sh * Sw * Sc * (1.0f / 8192.0f);
        const float coef = decay[c1] * (1.0f + spec_pe[c1 * 8 + c2] * mean) * sPow[abs(c1 - c2)];
        reinterpret_cast<float*>(sCoef)[t] = coef;
    }
    __syncthreads();

    // Output slice for this (h1,w1): 65536 floats; this CTA handles h2-half.
    float* __restrict__ outb = out + (size_t)tile * 65536;

    // One thread per (h2,w2) c2-row (8 floats = 32B = one STG.256).
    // 512 rows in this half / 512 threads: w2 = t&31, h2 = hHalf*16 + (t>>5).
    const int w2 = t & 31;
    const int h2 = (hHalf << 4) | (t >> 5);
    const float s = sPow[abs(h1 - h2)] * sPow[abs(w1 - w2)];
    float* const pBase = outb + (((h2 << 5) | w2) << 3);

    #pragma unroll
    for (int c1 = 0; c1 < 8; ++c1) {
        const float4 cfLo = sCoef[(c1 << 1) | 0];
        const float4 cfHi = sCoef[(c1 << 1) | 1];
        float* p = pBase + c1 * 8192;
        stg256wt(p, s * cfLo.x, s * cfLo.y, s * cfLo.z, s * cfLo.w,
                    s * cfHi.x, s * cfHi.y, s * cfHi.z, s * cfHi.w);
    }
}

extern "C" void kernel_launch(void* const* d_in, const int* in_sizes, int n_in,
                              void* d_out, int out_size) {
    // Inputs: x (unused, 524288 elems), decay (8), spec_pe (64) — identify by size.
    const float* decay   = nullptr;
    const float* spec_pe = nullptr;
    for (int i = 0; i < n_in; ++i) {
        if (in_sizes[i] == 8)       decay   = (const float*)d_in[i];
        else if (in_sizes[i] == 64) spec_pe = (const float*)d_in[i];
    }
    mrp3d_kernel<<<2048, 512>>>(decay, spec_pe, (float*)d_out);
}

// round 16
// speedup vs baseline: 1.0700x; 1.0128x over previous
#include <cuda_runtime.h>

// out[h1,w1,c1,h2,w2,c2] = g^(|dh|+|dw|+|dc|) * (1 + spec_pe[c1,c2]*mean[h1,w1,c1]) * decay[c1]
// mean[h1,w1,c1] = Sh[h1]*Sw[w1]*Sc[c1] / (H*W*C), closed-form geometric sums.
// H=W=32, C=8. Output: 1024 * 65536 floats = 268.4 MB, pure write-bound.
//
// R16 = R15 (grid 2048 x 512 thr, STG.256 .wt — best bench 43.07us) with all
// setup replaced by closed forms: no sPow shared table, no serial pow chain,
// no 72-iter LDS reduction, ONE barrier instead of two. Geometric sum
// S(x) = [(1-g^(x+1)) + (g - g^(N-x))]/(1-g) via __powf; per-thread store
// scale = single __powf(g, |dh|+|dw|). rel_err rises ~8e-8 -> ~1e-6 (tol 1e-3).

#define GAMMA 0.9f
#define INV_1MG (1.0f / (1.0f - GAMMA))   // 10

__device__ __forceinline__ void stg256wt(float* p, float x0, float x1, float x2, float x3,
                                         float x4, float x5, float x6, float x7) {
    asm volatile("st.global.wt.v8.b32 [%0], {%1,%2,%3,%4,%5,%6,%7,%8};"
                 :: "l"(p),
                    "r"(__float_as_uint(x0)), "r"(__float_as_uint(x1)),
                    "r"(__float_as_uint(x2)), "r"(__float_as_uint(x3)),
                    "r"(__float_as_uint(x4)), "r"(__float_as_uint(x5)),
                    "r"(__float_as_uint(x6)), "r"(__float_as_uint(x7))
                 : "memory");
}

// Sum_{j=0}^{N-1} gamma^|x-j| in closed form
__device__ __forceinline__ float geosum(int x, int N) {
    return ((1.0f - __powf(GAMMA, (float)(x + 1))) +
            (GAMMA - __powf(GAMMA, (float)(N - x)))) * INV_1MG;
}

__global__ __launch_bounds__(512) void mrp3d_kernel(const float* __restrict__ decay,
                                                    const float* __restrict__ spec_pe,
                                                    float* __restrict__ out) {
    __shared__ float4 sCoef[16];  // fused coef [c1][c2-half]: decay*(1+spec*mean)*g^|c1-c2|

    const int tile  = blockIdx.x >> 1;   // (h1,w1) tile index, 0..1023
    const int hHalf = blockIdx.x & 1;    // which h2 half: [0,16) or [16,32)
    const int h1 = tile >> 5;
    const int w1 = tile & 31;
    const int t  = threadIdx.x;

    // Build fused 8x8 coefficient table for this (h1,w1) — closed form, no table.
    if (t < 64) {
        const int c1 = t >> 3;
        const int c2 = t & 7;
        const float mean = geosum(h1, 32) * geosum(w1, 32) * geosum(c1, 8) * (1.0f / 8192.0f);
        const float coef = decay[c1] * (1.0f + spec_pe[c1 * 8 + c2] * mean)
                         * __powf(GAMMA, (float)abs(c1 - c2));
        reinterpret_cast<float*>(sCoef)[t] = coef;
    }

    // Per-thread store scale (independent of sCoef; computed before the barrier).
    // One thread per (h2,w2) c2-row: w2 = t&31, h2 = hHalf*16 + (t>>5).
    const int w2 = t & 31;
    const int h2 = (hHalf << 4) | (t >> 5);
    const float s = __powf(GAMMA, (float)(abs(h1 - h2) + abs(w1 - w2)));

    __syncthreads();

    // Output slice for this (h1,w1): 65536 floats; this CTA handles one h2-half.
    float* __restrict__ outb = out + (size_t)tile * 65536;
    float* const pBase = outb + (((h2 << 5) | w2) << 3);

    #pragma unroll
    for (int c1 = 0; c1 < 8; ++c1) {
        const float4 cfLo = sCoef[(c1 << 1) | 0];
        const float4 cfHi = sCoef[(c1 << 1) | 1];
        float* p = pBase + c1 * 8192;
        stg256wt(p, s * cfLo.x, s * cfLo.y, s * cfLo.z, s * cfLo.w,
                    s * cfHi.x, s * cfHi.y, s * cfHi.z, s * cfHi.w);
    }
}

extern "C" void kernel_launch(void* const* d_in, const int* in_sizes, int n_in,
                              void* d_out, int out_size) {
    // Inputs: x (unused, 524288 elems), decay (8), spec_pe (64) — identify by size.
    const float* decay   = nullptr;
    const float* spec_pe = nullptr;
    for (int i = 0; i < n_in; ++i) {
        if (in_sizes[i] == 8)       decay   = (const float*)d_in[i];
        else if (in_sizes[i] == 64) spec_pe = (const float*)d_in[i];
    }
    mrp3d_kernel<<<2048, 512>>>(decay, spec_pe, (float*)d_out);
}